// round 3
// baseline (speedup 1.0000x reference)
#include <cuda_runtime.h>
#include <cstdint>

#define N_BOX 9216
#define NW 144            // 9216/64 mask words per row
#define SORT_N 16384

// ---------------- device scratch (no allocations allowed) ----------------
__device__ float g_x[512 * 1024];                      // conv output (relu'd)
__device__ float g_bbox[36 * 1024];                    // bbox head output
__device__ float4 g_boxes[N_BOX];                      // clipped proposals, original order
__device__ float4 g_sbox[N_BOX];                       // sorted boxes
__device__ float  g_sarea[N_BOX];
__device__ int    g_sorder[N_BOX];
__device__ unsigned long long g_keys[SORT_N];
__device__ unsigned long long g_mask[(size_t)N_BOX * NW];  // 10.6 MB suppression bitmask
__device__ unsigned long long g_keepw[NW];

// ---------------- 3x3 conv + bias + relu ----------------
// grid (32 oc-tiles, 8 row-tiles), 256 threads.
// block computes 16 output channels x 4 rows x 32 cols.
// thread = (xg:8, rr:4, og:8) -> 2 oc x 4 px register tile.
__global__ __launch_bounds__(256) void k_conv(const float* __restrict__ feat,
                                              const float* __restrict__ W,
                                              const float* __restrict__ B) {
    __shared__ float sf[8][6][35];   // 8 in-ch x (4 rows + halo) x (32 + halo, padded to 35)
    __shared__ float sw[16][8][9];   // 16 oc x 8 in-ch x 9 taps
    const int tid = threadIdx.x;
    const int oc0 = blockIdx.x * 16;
    const int y0 = blockIdx.y * 4;
    const int xg = tid & 7, rr = (tid >> 3) & 3, og = tid >> 5;
    const int x0 = xg * 4;

    float acc[2][4];
#pragma unroll
    for (int a = 0; a < 2; a++)
#pragma unroll
        for (int b = 0; b < 4; b++) acc[a][b] = 0.f;

    for (int c0 = 0; c0 < 256; c0 += 8) {
        __syncthreads();
        // stage features (zero-padded halo)
        for (int i = tid; i < 8 * 6 * 35; i += 256) {
            int cc = i / 210, rem = i % 210, ry = rem / 35, rx = rem % 35;
            float v = 0.f;
            int gy = y0 + ry - 1, gx = rx - 1;
            if (rx < 34 && (unsigned)gy < 32u && (unsigned)gx < 32u)
                v = feat[(c0 + cc) * 1024 + gy * 32 + gx];
            (&sf[0][0][0])[i] = v;
        }
        // stage weights
        for (int i = tid; i < 16 * 8 * 9; i += 256) {
            int o = i / 72, rem = i % 72;
            (&sw[0][0][0])[i] = W[(oc0 + o) * 2304 + c0 * 9 + rem];
        }
        __syncthreads();

#pragma unroll
        for (int cc = 0; cc < 8; cc++) {
            float f[3][6];
#pragma unroll
            for (int dy = 0; dy < 3; dy++)
#pragma unroll
                for (int dx = 0; dx < 6; dx++)
                    f[dy][dx] = sf[cc][rr + dy][x0 + dx];
#pragma unroll
            for (int o2 = 0; o2 < 2; o2++) {
                const float* wp = sw[og * 2 + o2][cc];  // uniform per warp -> broadcast
                float w0 = wp[0], w1 = wp[1], w2 = wp[2], w3 = wp[3], w4 = wp[4];
                float w5 = wp[5], w6 = wp[6], w7 = wp[7], w8 = wp[8];
#pragma unroll
                for (int p = 0; p < 4; p++) {
                    float s = acc[o2][p];
                    s += w0 * f[0][p]; s += w1 * f[0][p + 1]; s += w2 * f[0][p + 2];
                    s += w3 * f[1][p]; s += w4 * f[1][p + 1]; s += w5 * f[1][p + 2];
                    s += w6 * f[2][p]; s += w7 * f[2][p + 1]; s += w8 * f[2][p + 2];
                    acc[o2][p] = s;
                }
            }
        }
    }

    const int y = y0 + rr;
#pragma unroll
    for (int o2 = 0; o2 < 2; o2++) {
        int oc = oc0 + og * 2 + o2;
        float b = B[oc];
#pragma unroll
        for (int p = 0; p < 4; p++) {
            float v = acc[o2][p] + b;
            g_x[oc * 1024 + y * 32 + x0 + p] = v > 0.f ? v : 0.f;
        }
    }
}

// ---------------- 1x1 heads: logits->sigmoid probs (into out), bbox deltas ----------------
// grid 32 (32 px each), 256 threads = 32 px lanes x 8 c-chunks of 64.
__global__ __launch_bounds__(256) void k_heads(const float* __restrict__ cw,
                                               const float* __restrict__ cbv,
                                               const float* __restrict__ bw,
                                               const float* __restrict__ bbv,
                                               float* __restrict__ out) {
    __shared__ float red[54][32];
    const int tid = threadIdx.x;
    const int lane = tid & 31, sub = tid >> 5;
    const int px = blockIdx.x * 32 + lane;

    float ac[18], ab[36];
#pragma unroll
    for (int o = 0; o < 18; o++) ac[o] = 0.f;
#pragma unroll
    for (int o = 0; o < 36; o++) ab[o] = 0.f;

    const int cbeg = sub * 64;
    for (int c = cbeg; c < cbeg + 64; c++) {
        float xv = g_x[c * 1024 + px];
#pragma unroll
        for (int o = 0; o < 18; o++) ac[o] += __ldg(cw + o * 512 + c) * xv;
#pragma unroll
        for (int o = 0; o < 36; o++) ab[o] += __ldg(bw + o * 512 + c) * xv;
    }

    for (int j = tid; j < 54 * 32; j += 256) (&red[0][0])[j] = 0.f;
    __syncthreads();
    // deterministic fixed-order accumulation over the 8 c-chunks
    for (int k = 0; k < 8; k++) {
        if (sub == k) {
#pragma unroll
            for (int o = 0; o < 18; o++) red[o][lane] += ac[o];
#pragma unroll
            for (int o = 0; o < 36; o++) red[18 + o][lane] += ab[o];
        }
        __syncthreads();
    }
    for (int j = tid; j < 54 * 32; j += 256) {
        int o = j >> 5, p = j & 31;
        int gpx = blockIdx.x * 32 + p;
        float s = red[o][p];
        if (o < 18) {
            float v = s + cbv[o];
            out[36864 + o * 1024 + gpx] = 1.f / (1.f + expf(-v));
        } else {
            int ob = o - 18;
            g_bbox[ob * 1024 + gpx] = s + bbv[ob];
        }
    }
}

// ---------------- decode boxes + clip + sort keys ----------------
__global__ void k_prop(const float* __restrict__ out, const int* __restrict__ imgsz) {
    int r = blockIdx.x * blockDim.x + threadIdx.x;
    if (r >= N_BOX) return;
    int isz = imgsz[0];
    float img = (float)isz;
    float strd = (float)(isz / 32);

    // fg score pairing: probs[:,1::2].reshape(-1) -> a = r/1024, s = r%1024
    int a = r >> 10, s = r & 1023;
    float score = out[36864 + (2 * a + 1) * 1024 + s];

    // deltas: bbox(1,36,32,32).reshape(-1,4): channel c0=r/256, spatial 4*(r%256)+k
    int c0 = r >> 8, s0 = (r & 255) << 2;
    const float* bp = g_bbox + c0 * 1024 + s0;
    float dx = bp[0], dyv = bp[1], dw = bp[2], dh = bp[3];

    // anchors: spatial-major, anchor-minor; ratio-major over scales, rounded (half-even)
    int sa = r / 9, aa = r - sa * 9;
    int ix = sa & 31, iy = sa >> 5;
    const float ratios[3] = {0.5f, 1.f, 2.f};
    const float scales[3] = {128.f, 256.f, 512.f};
    float ratio = ratios[aa / 3], scale = scales[aa % 3];
    float hr = sqrtf(ratio), wr = 1.f / hr;
    float w2 = rintf(0.5f * (wr * scale));
    float h2 = rintf(0.5f * (hr * scale));
    float shx = ix * strd, shy = iy * strd;
    float x1 = shx - w2, y1 = shy - h2, x2 = shx + w2, y2 = shy + h2;

    float w = x2 - x1, h = y2 - y1;
    float cx = x1 + 0.5f * w, cy = y1 + 0.5f * h;
    float pcx = dx * w + cx, pcy = dyv * h + cy;
    float pw = expf(dw) * w, ph = expf(dh) * h;
    float bx1 = pcx - 0.5f * pw, by1 = pcy - 0.5f * ph;
    float bx2 = pcx + 0.5f * pw, by2 = pcy + 0.5f * ph;
    bx1 = fminf(fmaxf(bx1, 0.f), img); by1 = fminf(fmaxf(by1, 0.f), img);
    bx2 = fminf(fmaxf(bx2, 0.f), img); by2 = fminf(fmaxf(by2, 0.f), img);

    g_boxes[r] = make_float4(bx1, by1, bx2, by2);
    // key: score descending (positive float -> ~bits monotone decreasing), idx ascending on ties
    unsigned int sb = __float_as_uint(score);
    g_keys[r] = ((unsigned long long)(~sb) << 32) | (unsigned int)r;
}

// ---------------- single-block bitonic sort (16384 keys in 128KB smem) ----------------
__global__ __launch_bounds__(1024) void k_sort() {
    extern __shared__ unsigned long long sk[];
    const int tid = threadIdx.x;
    for (int i = tid; i < SORT_N; i += 1024)
        sk[i] = (i < N_BOX) ? g_keys[i] : 0xFFFFFFFFFFFFFFFFull;
    __syncthreads();
    for (int k = 2; k <= SORT_N; k <<= 1) {
        for (int j = k >> 1; j > 0; j >>= 1) {
            for (int i = tid; i < SORT_N; i += 1024) {
                int p = i ^ j;
                if (p > i) {
                    unsigned long long A = sk[i], Bv = sk[p];
                    bool up = ((i & k) == 0);
                    if ((A > Bv) == up) { sk[i] = Bv; sk[p] = A; }
                }
            }
            __syncthreads();
        }
    }
    for (int i = tid; i < N_BOX; i += 1024) g_keys[i] = sk[i];
}

// ---------------- gather sorted boxes ----------------
__global__ void k_gather() {
    int r = blockIdx.x * blockDim.x + threadIdx.x;
    if (r >= N_BOX) return;
    unsigned long long kk = g_keys[r];
    int orig = (int)(unsigned int)kk;
    g_sorder[r] = orig;
    float4 b = g_boxes[orig];
    g_sbox[r] = b;
    g_sarea[r] = (b.z - b.x) * (b.w - b.y);
}

// ---------------- NMS suppression bitmask (upper-triangular 64x64 tiles) ----------------
__global__ __launch_bounds__(64) void k_mask() {
    const int rb = blockIdx.y, cb = blockIdx.x;
    if (cb < rb) return;
    __shared__ float4 cbox[64];
    __shared__ float carea[64];
    const int t = threadIdx.x;
    const int j0 = cb * 64;
    cbox[t] = g_sbox[j0 + t];
    carea[t] = g_sarea[j0 + t];
    __syncthreads();

    const int i = rb * 64 + t;
    float4 bi = g_sbox[i];
    float ai = g_sarea[i];
    unsigned long long bits = 0;
#pragma unroll 4
    for (int jj = 0; jj < 64; ++jj) {
        int j = j0 + jj;
        if (j > i) {
            float4 bj = cbox[jj];
            float xx1 = fmaxf(bi.x, bj.x), yy1 = fmaxf(bi.y, bj.y);
            float xx2 = fminf(bi.z, bj.z), yy2 = fminf(bi.w, bj.w);
            float w = fmaxf(xx2 - xx1, 0.f), h = fmaxf(yy2 - yy1, 0.f);
            float inter = w * h;
            float iou = inter / (ai + carea[jj] - inter + 1e-9f);  // IEEE div like ref
            if (iou > 0.3f) bits |= 1ull << jj;
        }
    }
    g_mask[(size_t)i * NW + cb] = bits;
}

// ---------------- greedy sequential reduce (single block) ----------------
__global__ __launch_bounds__(256) void k_reduce() {
    __shared__ unsigned long long remv[NW];
    __shared__ unsigned long long diag[64];
    __shared__ int s_kept[64];
    __shared__ int s_cnt;
    const int t = threadIdx.x;
    if (t < NW) remv[t] = 0;
    __syncthreads();

    for (int rb = 0; rb < NW; ++rb) {
        if (t < 64) diag[t] = g_mask[(size_t)(rb * 64 + t) * NW + rb];
        __syncthreads();
        if (t == 0) {
            unsigned long long rm = remv[rb];
            unsigned long long keep = 0;
            int cnt = 0;
            unsigned long long avail = ~rm;
            while (avail) {
                int b = __ffsll((long long)avail) - 1;
                keep |= 1ull << b;
                s_kept[cnt++] = rb * 64 + b;
                avail &= ~(diag[b] | (1ull << b));
            }
            s_cnt = cnt;
            g_keepw[rb] = keep;
        }
        __syncthreads();
        const int cnt = s_cnt;
        if (t > rb && t < NW) {
            unsigned long long accv = remv[t];
#pragma unroll 4
            for (int k = 0; k < cnt; k++)
                accv |= g_mask[(size_t)s_kept[k] * NW + t];
            remv[t] = accv;
        }
        __syncthreads();
    }
}

// ---------------- finalize: scatter keep to original order, write outputs ----------------
__global__ void k_final(float* __restrict__ out) {
    int r = blockIdx.x * blockDim.x + threadIdx.x;
    if (r >= N_BOX) return;
    int orig = g_sorder[r];
    float m = (float)((g_keepw[r >> 6] >> (r & 63)) & 1ull);
    float4 b = g_boxes[orig];
    out[4 * orig + 0] = b.x * m;
    out[4 * orig + 1] = b.y * m;
    out[4 * orig + 2] = b.z * m;
    out[4 * orig + 3] = b.w * m;
    out[55296 + orig] = m;
}

// ---------------- launcher ----------------
extern "C" void kernel_launch(void* const* d_in, const int* in_sizes, int n_in,
                              void* d_out, int out_size) {
    const float* feat   = (const float*)d_in[0];
    const int*   imgsz  = (const int*)d_in[1];
    const float* conv_w = (const float*)d_in[2];
    const float* conv_b = (const float*)d_in[3];
    const float* cls_w  = (const float*)d_in[4];
    const float* cls_b  = (const float*)d_in[5];
    const float* bbox_w = (const float*)d_in[6];
    const float* bbox_b = (const float*)d_in[7];
    float* out = (float*)d_out;

    cudaFuncSetAttribute(k_sort, cudaFuncAttributeMaxDynamicSharedMemorySize,
                         SORT_N * (int)sizeof(unsigned long long));

    k_conv<<<dim3(32, 8), 256>>>(feat, conv_w, conv_b);
    k_heads<<<32, 256>>>(cls_w, cls_b, bbox_w, bbox_b, out);
    k_prop<<<36, 256>>>(out, imgsz);
    k_sort<<<1, 1024, SORT_N * sizeof(unsigned long long)>>>();
    k_gather<<<36, 256>>>();
    k_mask<<<dim3(NW, NW), 64>>>();
    k_reduce<<<1, 256>>>();
    k_final<<<36, 256>>>(out);
}

// round 4
// speedup vs baseline: 1.5636x; 1.5636x over previous
#include <cuda_runtime.h>
#include <cstdint>

#define N_BOX 9216
#define NW 144            // 9216/64 mask words per row

// ---------------- device scratch (no allocations allowed) ----------------
__device__ float g_x[512 * 1024];                      // conv output (relu'd)
__device__ float g_bbox[36 * 1024];                    // bbox head output
__device__ float4 g_boxes[N_BOX];                      // clipped proposals, original order
__device__ float4 g_sbox[N_BOX];                       // sorted boxes
__device__ float  g_sarea[N_BOX];
__device__ int    g_sorder[N_BOX];
__device__ int    g_rank[N_BOX];
__device__ unsigned long long g_keys[N_BOX];
__device__ unsigned long long g_mask[(size_t)N_BOX * NW];  // 10.6 MB suppression bitmask
__device__ unsigned long long g_diag[N_BOX];               // compact diagonal words
__device__ unsigned long long g_keepw[NW];

// ---------------- 3x3 conv + bias + relu ----------------
// grid (32 oc-tiles, 8 row-tiles), 256 threads.
// block computes 16 output channels x 4 rows x 32 cols.
__global__ __launch_bounds__(256) void k_conv(const float* __restrict__ feat,
                                              const float* __restrict__ W,
                                              const float* __restrict__ B) {
    __shared__ float sf[8][6][35];   // 8 in-ch x (4 rows + halo) x (32 + halo, padded)
    __shared__ float sw[16][8][9];   // 16 oc x 8 in-ch x 9 taps
    const int tid = threadIdx.x;
    const int oc0 = blockIdx.x * 16;
    const int y0 = blockIdx.y * 4;
    const int xg = tid & 7, rr = (tid >> 3) & 3, og = tid >> 5;
    const int x0 = xg * 4;

    float acc[2][4];
#pragma unroll
    for (int a = 0; a < 2; a++)
#pragma unroll
        for (int b = 0; b < 4; b++) acc[a][b] = 0.f;

    for (int c0 = 0; c0 < 256; c0 += 8) {
        __syncthreads();
        for (int i = tid; i < 8 * 6 * 35; i += 256) {
            int cc = i / 210, rem = i % 210, ry = rem / 35, rx = rem % 35;
            float v = 0.f;
            int gy = y0 + ry - 1, gx = rx - 1;
            if (rx < 34 && (unsigned)gy < 32u && (unsigned)gx < 32u)
                v = feat[(c0 + cc) * 1024 + gy * 32 + gx];
            (&sf[0][0][0])[i] = v;
        }
        for (int i = tid; i < 16 * 8 * 9; i += 256) {
            int o = i / 72, rem = i % 72;
            (&sw[0][0][0])[i] = W[(oc0 + o) * 2304 + c0 * 9 + rem];
        }
        __syncthreads();

#pragma unroll
        for (int cc = 0; cc < 8; cc++) {
            float f[3][6];
#pragma unroll
            for (int dy = 0; dy < 3; dy++)
#pragma unroll
                for (int dx = 0; dx < 6; dx++)
                    f[dy][dx] = sf[cc][rr + dy][x0 + dx];
#pragma unroll
            for (int o2 = 0; o2 < 2; o2++) {
                const float* wp = sw[og * 2 + o2][cc];  // uniform per warp -> LDS broadcast
                float w0 = wp[0], w1 = wp[1], w2 = wp[2], w3 = wp[3], w4 = wp[4];
                float w5 = wp[5], w6 = wp[6], w7 = wp[7], w8 = wp[8];
#pragma unroll
                for (int p = 0; p < 4; p++) {
                    float s = acc[o2][p];
                    s += w0 * f[0][p]; s += w1 * f[0][p + 1]; s += w2 * f[0][p + 2];
                    s += w3 * f[1][p]; s += w4 * f[1][p + 1]; s += w5 * f[1][p + 2];
                    s += w6 * f[2][p]; s += w7 * f[2][p + 1]; s += w8 * f[2][p + 2];
                    acc[o2][p] = s;
                }
            }
        }
    }

    const int y = y0 + rr;
#pragma unroll
    for (int o2 = 0; o2 < 2; o2++) {
        int oc = oc0 + og * 2 + o2;
        float b = B[oc];
#pragma unroll
        for (int p = 0; p < 4; p++) {
            float v = acc[o2][p] + b;
            g_x[oc * 1024 + y * 32 + x0 + p] = v > 0.f ? v : 0.f;
        }
    }
}

// ---------------- 1x1 heads ----------------
__global__ __launch_bounds__(256) void k_heads(const float* __restrict__ cw,
                                               const float* __restrict__ cbv,
                                               const float* __restrict__ bw,
                                               const float* __restrict__ bbv,
                                               float* __restrict__ out) {
    __shared__ float red[54][32];
    const int tid = threadIdx.x;
    const int lane = tid & 31, sub = tid >> 5;
    const int px = blockIdx.x * 32 + lane;

    float ac[18], ab[36];
#pragma unroll
    for (int o = 0; o < 18; o++) ac[o] = 0.f;
#pragma unroll
    for (int o = 0; o < 36; o++) ab[o] = 0.f;

    const int cbeg = sub * 64;
    for (int c = cbeg; c < cbeg + 64; c++) {
        float xv = g_x[c * 1024 + px];
#pragma unroll
        for (int o = 0; o < 18; o++) ac[o] += __ldg(cw + o * 512 + c) * xv;
#pragma unroll
        for (int o = 0; o < 36; o++) ab[o] += __ldg(bw + o * 512 + c) * xv;
    }

    for (int j = tid; j < 54 * 32; j += 256) (&red[0][0])[j] = 0.f;
    __syncthreads();
    for (int k = 0; k < 8; k++) {   // deterministic fixed-order accumulation
        if (sub == k) {
#pragma unroll
            for (int o = 0; o < 18; o++) red[o][lane] += ac[o];
#pragma unroll
            for (int o = 0; o < 36; o++) red[18 + o][lane] += ab[o];
        }
        __syncthreads();
    }
    for (int j = tid; j < 54 * 32; j += 256) {
        int o = j >> 5, p = j & 31;
        int gpx = blockIdx.x * 32 + p;
        float s = red[o][p];
        if (o < 18) {
            float v = s + cbv[o];
            out[36864 + o * 1024 + gpx] = 1.f / (1.f + expf(-v));
        } else {
            int ob = o - 18;
            g_bbox[ob * 1024 + gpx] = s + bbv[ob];
        }
    }
}

// ---------------- decode boxes + clip + sort keys (+ zero rank) ----------------
__global__ void k_prop(const float* __restrict__ out, const int* __restrict__ imgsz) {
    int r = blockIdx.x * blockDim.x + threadIdx.x;
    if (r >= N_BOX) return;
    int isz = imgsz[0];
    float img = (float)isz;
    float strd = (float)(isz / 32);

    int a = r >> 10, s = r & 1023;
    float score = out[36864 + (2 * a + 1) * 1024 + s];

    int c0 = r >> 8, s0 = (r & 255) << 2;
    const float* bp = g_bbox + c0 * 1024 + s0;
    float dx = bp[0], dyv = bp[1], dw = bp[2], dh = bp[3];

    int sa = r / 9, aa = r - sa * 9;
    int ix = sa & 31, iy = sa >> 5;
    const float ratios[3] = {0.5f, 1.f, 2.f};
    const float scales[3] = {128.f, 256.f, 512.f};
    float ratio = ratios[aa / 3], scale = scales[aa % 3];
    float hr = sqrtf(ratio), wr = 1.f / hr;
    float w2 = rintf(0.5f * (wr * scale));
    float h2 = rintf(0.5f * (hr * scale));
    float shx = ix * strd, shy = iy * strd;
    float x1 = shx - w2, y1 = shy - h2, x2 = shx + w2, y2 = shy + h2;

    float w = x2 - x1, h = y2 - y1;
    float cx = x1 + 0.5f * w, cy = y1 + 0.5f * h;
    float pcx = dx * w + cx, pcy = dyv * h + cy;
    float pw = expf(dw) * w, ph = expf(dh) * h;
    float bx1 = pcx - 0.5f * pw, by1 = pcy - 0.5f * ph;
    float bx2 = pcx + 0.5f * pw, by2 = pcy + 0.5f * ph;
    bx1 = fminf(fmaxf(bx1, 0.f), img); by1 = fminf(fmaxf(by1, 0.f), img);
    bx2 = fminf(fmaxf(bx2, 0.f), img); by2 = fminf(fmaxf(by2, 0.f), img);

    g_boxes[r] = make_float4(bx1, by1, bx2, by2);
    unsigned int sb = __float_as_uint(score);
    g_keys[r] = ((unsigned long long)(~sb) << 32) | (unsigned int)r;
    g_rank[r] = 0;
}

// ---------------- rank by counting (replaces 178us bitonic sort) ----------------
// grid (36, 4): 36 i-tiles of 256, 4 j-chunks of 2304. All keys distinct, so
// rank[i] = #{j : key[j] < key[i]} is the exact sorted position.
__global__ __launch_bounds__(256) void k_rank() {
    __shared__ unsigned long long sk[2304];
    const int tid = threadIdx.x;
    const int jbase = blockIdx.y * 2304;
    for (int j = tid; j < 2304; j += 256) sk[j] = g_keys[jbase + j];
    __syncthreads();
    const int i = blockIdx.x * 256 + tid;
    const unsigned long long ki = g_keys[i];
    int c0 = 0, c1 = 0, c2 = 0, c3 = 0;
#pragma unroll 4
    for (int j = 0; j < 2304; j += 4) {   // all lanes same addr -> LDS broadcast
        c0 += (sk[j]     < ki);
        c1 += (sk[j + 1] < ki);
        c2 += (sk[j + 2] < ki);
        c3 += (sk[j + 3] < ki);
    }
    atomicAdd(&g_rank[i], c0 + c1 + c2 + c3);
}

// ---------------- scatter into sorted order ----------------
__global__ void k_scatter() {
    int r = blockIdx.x * blockDim.x + threadIdx.x;
    if (r >= N_BOX) return;
    int rk = g_rank[r];
    g_sorder[rk] = r;
    float4 b = g_boxes[r];
    g_sbox[rk] = b;
    g_sarea[rk] = (b.z - b.x) * (b.w - b.y);
}

// ---------------- NMS suppression bitmask (upper-triangular 64x64 tiles) ----------------
__global__ __launch_bounds__(64) void k_mask() {
    const int rb = blockIdx.y, cb = blockIdx.x;
    if (cb < rb) return;
    __shared__ float4 cbox[64];
    __shared__ float carea[64];
    const int t = threadIdx.x;
    const int j0 = cb * 64;
    cbox[t] = g_sbox[j0 + t];
    carea[t] = g_sarea[j0 + t];
    __syncthreads();

    const int i = rb * 64 + t;
    float4 bi = g_sbox[i];
    float ai = g_sarea[i];
    unsigned long long bits = 0;
#pragma unroll 4
    for (int jj = 0; jj < 64; ++jj) {
        int j = j0 + jj;
        if (j > i) {
            float4 bj = cbox[jj];
            float xx1 = fmaxf(bi.x, bj.x), yy1 = fmaxf(bi.y, bj.y);
            float xx2 = fminf(bi.z, bj.z), yy2 = fminf(bi.w, bj.w);
            float w = fmaxf(xx2 - xx1, 0.f), h = fmaxf(yy2 - yy1, 0.f);
            float inter = w * h;
            float iou = inter / (ai + carea[jj] - inter + 1e-9f);
            if (iou > 0.3f) bits |= 1ull << jj;
        }
    }
    g_mask[(size_t)i * NW + cb] = bits;
    if (cb == rb) g_diag[i] = bits;   // compact diagonal for the reduce preload
}

// ---------------- greedy reduce: diag in smem, 7-way parallel OR phase ----------------
__global__ __launch_bounds__(1024) void k_reduce() {
    extern __shared__ unsigned long long sdiag[];   // 9216 words = 73.7KB
    __shared__ unsigned long long remv[NW];
    __shared__ int s_kept[64];
    __shared__ int s_cnt;
    const int t = threadIdx.x;
    for (int i = t; i < N_BOX; i += 1024) sdiag[i] = g_diag[i];
    if (t < NW) remv[t] = 0;
    __syncthreads();

    const int g = t / NW;            // group 0..6 (t < 1008)
    const int w = t - g * NW;        // word index 0..143

    for (int rb = 0; rb < NW; ++rb) {
        if (t == 0) {
            unsigned long long keep = 0;
            int cnt = 0;
            unsigned long long avail = ~remv[rb];
            const unsigned long long* dg = sdiag + rb * 64;
            while (avail) {
                int b = __ffsll((long long)avail) - 1;
                keep |= 1ull << b;
                s_kept[cnt++] = rb * 64 + b;
                avail &= ~(dg[b] | (1ull << b));
            }
            s_cnt = cnt;
            g_keepw[rb] = keep;
        }
        __syncthreads();
        const int cnt = s_cnt;
        if (t < 1008 && w > rb && cnt > g) {
            unsigned long long acc = 0;
            for (int k = g; k < cnt; k += 7)     // coalesced across w per k
                acc |= g_mask[(size_t)s_kept[k] * NW + w];
            if (acc) atomicOr(&remv[w], acc);
        }
        __syncthreads();
    }
}

// ---------------- finalize ----------------
__global__ void k_final(float* __restrict__ out) {
    int r = blockIdx.x * blockDim.x + threadIdx.x;
    if (r >= N_BOX) return;
    int orig = g_sorder[r];
    float m = (float)((g_keepw[r >> 6] >> (r & 63)) & 1ull);
    float4 b = g_boxes[orig];
    out[4 * orig + 0] = b.x * m;
    out[4 * orig + 1] = b.y * m;
    out[4 * orig + 2] = b.z * m;
    out[4 * orig + 3] = b.w * m;
    out[55296 + orig] = m;
}

// ---------------- launcher ----------------
extern "C" void kernel_launch(void* const* d_in, const int* in_sizes, int n_in,
                              void* d_out, int out_size) {
    const float* feat   = (const float*)d_in[0];
    const int*   imgsz  = (const int*)d_in[1];
    const float* conv_w = (const float*)d_in[2];
    const float* conv_b = (const float*)d_in[3];
    const float* cls_w  = (const float*)d_in[4];
    const float* cls_b  = (const float*)d_in[5];
    const float* bbox_w = (const float*)d_in[6];
    const float* bbox_b = (const float*)d_in[7];
    float* out = (float*)d_out;

    cudaFuncSetAttribute(k_reduce, cudaFuncAttributeMaxDynamicSharedMemorySize,
                         N_BOX * (int)sizeof(unsigned long long));

    k_conv<<<dim3(32, 8), 256>>>(feat, conv_w, conv_b);
    k_heads<<<32, 256>>>(cls_w, cls_b, bbox_w, bbox_b, out);
    k_prop<<<36, 256>>>(out, imgsz);
    k_rank<<<dim3(36, 4), 256>>>();
    k_scatter<<<36, 256>>>();
    k_mask<<<dim3(NW, NW), 64>>>();
    k_reduce<<<1, 1024, N_BOX * sizeof(unsigned long long)>>>();
    k_final<<<36, 256>>>(out);
}